// round 8
// baseline (speedup 1.0000x reference)
#include <cuda_runtime.h>

#define Nn 128
#define Tn 2048
#define Bn 64

// Precomputed exp-domain constants (written by prep_kernel each launch).
__device__ __align__(16) float g_ET[Nn * Nn];  // ET[j*N+i] (col-major: fwd)
__device__ __align__(16) float g_E[Nn * Nn];   // E[i*N+j]  (row-major: bwd)
__device__ float g_stexp[Nn];
__device__ float g_enexp[Nn];

// Split-scan scratch.
__device__ __align__(16) float g_alpha[2 * Bn][Nn];
__device__ __align__(16) float g_wvec[2 * Bn][Nn];
__device__ int g_sexpF[2 * Bn];
__device__ int g_sexpB[2 * Bn];

__global__ void prep_kernel(const float* __restrict__ trans,
                            const float* __restrict__ st,
                            const float* __restrict__ en,
                            const int* __restrict__ ftr,
                            const int* __restrict__ fst,
                            const int* __restrict__ fen)
{
    int idx = blockIdx.x * blockDim.x + threadIdx.x;
    if (idx < Nn * Nn) {
        int i = idx >> 7;
        int j = idx & (Nn - 1);
        float x = ftr[idx] ? 0.0f : expf(trans[idx]);
        g_E[idx] = x;
        g_ET[j * Nn + i] = x;
    }
    if (idx < Nn) {
        g_stexp[idx] = fst[idx] ? 0.0f : expf(st[idx]);
        g_enexp[idx] = fen[idx] ? 0.0f : expf(en[idx]);
    }
}

__device__ __forceinline__ unsigned long long ffma2(unsigned long long a,
                                                    unsigned long long b,
                                                    unsigned long long c)
{
    unsigned long long d;
    asm("fma.rn.f32x2 %0, %1, %2, %3;" : "=l"(d) : "l"(a), "l"(b), "l"(c));
    return d;
}

__device__ __forceinline__ unsigned long long addf2(unsigned long long a,
                                                    unsigned long long b)
{
    unsigned long long d;
    asm("add.rn.f32x2 %0, %1, %2;" : "=l"(d) : "l"(a), "l"(b));
    return d;
}

__device__ __forceinline__ float unpack_add(unsigned long long a)
{
    float lo, hi;
    asm("mov.b64 {%0, %1}, %2;" : "=f"(lo), "=f"(hi) : "l"(a));
    return lo + hi;
}

// Dual-column matvec: one pass over U feeds both columns' accumulators.
#define MATVEC2(RB, SA, SB)                                                     \
    {                                                                           \
        const ulonglong2* uvec = (const ulonglong2*)U[RB];                      \
        unsigned long long a0 = 0ull, a1 = 0ull, a2 = 0ull, a3 = 0ull;          \
        unsigned long long c0 = 0ull, c1 = 0ull, c2 = 0ull, c3 = 0ull;          \
        _Pragma("unroll")                                                       \
        for (int k = 0; k < 32; k += 2) {                                       \
            ulonglong2 u0 = uvec[k];                                            \
            ulonglong2 u1 = uvec[k + 1];                                        \
            a0 = ffma2(Ep0[k].x,     u0.x, a0);                                 \
            a1 = ffma2(Ep0[k].y,     u0.y, a1);                                 \
            c0 = ffma2(Ep1[k].x,     u0.x, c0);                                 \
            c1 = ffma2(Ep1[k].y,     u0.y, c1);                                 \
            a2 = ffma2(Ep0[k + 1].x, u1.x, a2);                                 \
            a3 = ffma2(Ep0[k + 1].y, u1.y, a3);                                 \
            c2 = ffma2(Ep1[k + 1].x, u1.x, c2);                                 \
            c3 = ffma2(Ep1[k + 1].y, u1.y, c3);                                 \
        }                                                                       \
        SA = unpack_add(addf2(addf2(a0, a1), addf2(a2, a3)));                   \
        SB = unpack_add(addf2(addf2(c0, c1), addf2(c2, c3)));                   \
    }

// Forward step, 2 columns per thread. MODE: 0 plain, 1 apply scale, 2 new max.
#define FSTEP(TSTEP, EA, TA, EB, TB, RB, WB, MODE)                              \
    {                                                                           \
        float pa = __expf(EA);                                                  \
        float pb = __expf(EB);                                                  \
        if (sup) {                                                              \
            if ((TA) == 0) pa = 0.0f;                                           \
            if ((TB) == 0) pb = 0.0f;                                           \
        }                                                                       \
        int tp = (TSTEP) + 4; if (tp > Tn - 1) tp = Tn - 1;                     \
        EA = emrow0[tp * Nn]; TA = tgrow0[tp * Nn];                             \
        EB = emrow1[tp * Nn]; TB = tgrow1[tp * Nn];                             \
        if ((MODE) == 1) { pa *= inv_pend; pb *= inv_pend; Sexp += e_pend; }    \
        float sA, sB;                                                           \
        MATVEC2(RB, sA, sB)                                                     \
        v0 = sA * pa;                                                           \
        v1 = sB * pb;                                                           \
        U[WB][col0] = v0;                                                       \
        U[WB][col1] = v1;                                                       \
        if ((MODE) == 2) {                                                      \
            unsigned int um = max(__float_as_uint(v0), __float_as_uint(v1));    \
            unsigned int wmu = __reduce_max_sync(0xffffffffu, um);              \
            if (lane == 0) wmaxbuf[warp] = wmu;                                 \
        }                                                                       \
        __syncthreads();                                                        \
        if ((MODE) == 2) {                                                      \
            unsigned int rm = max(wmaxbuf[0], wmaxbuf[1]);                      \
            e_pend = (int)(rm >> 23) - 127;                                     \
            inv_pend = __int_as_float((127 - e_pend) << 23);                    \
        }                                                                       \
        if ((TSTEP) == tendF) goto fin_f;                                       \
    }

// Backward step: w_{t-1} = E (p_t o w_t), 2 columns per thread.
#define BSTEP(TSTEP, EA, TA, EB, TB, WB, MODE)                                  \
    {                                                                           \
        float pa = __expf(EA);                                                  \
        float pb = __expf(EB);                                                  \
        if (sup) {                                                              \
            if ((TA) == 0) pa = 0.0f;                                           \
            if ((TB) == 0) pb = 0.0f;                                           \
        }                                                                       \
        int tp = (TSTEP) - 4; if (tp < 0) tp = 0;                               \
        EA = emrow0[tp * Nn]; TA = tgrow0[tp * Nn];                             \
        EB = emrow1[tp * Nn]; TB = tgrow1[tp * Nn];                             \
        U[WB][col0] = pa * v0;                                                  \
        U[WB][col1] = pb * v1;                                                  \
        __syncthreads();                                                        \
        if ((MODE) == 1) {                                                      \
            unsigned int rm = max(wmaxbuf[0], wmaxbuf[1]);                      \
            e_pend = (int)(rm >> 23) - 127;                                     \
            inv_pend = __int_as_float((127 - e_pend) << 23);                    \
            float sA, sB;                                                       \
            MATVEC2(WB, sA, sB)                                                 \
            v0 = sA * inv_pend;                                                 \
            v1 = sB * inv_pend;                                                 \
            Sexp += e_pend;                                                     \
        } else {                                                                \
            float sA, sB;                                                       \
            MATVEC2(WB, sA, sB)                                                 \
            v0 = sA;                                                            \
            v1 = sB;                                                            \
        }                                                                       \
        if ((MODE) == 2) {                                                      \
            unsigned int um = max(__float_as_uint(v0), __float_as_uint(v1));    \
            unsigned int wmu = __reduce_max_sync(0xffffffffu, um);              \
            if (lane == 0) wmaxbuf[warp] = wmu;                                 \
        }                                                                       \
        if ((TSTEP) == m) goto fin_b;                                           \
    }

__global__ void __launch_bounds__(64)
crf_scan_kernel(const float* __restrict__ em,
                const int* __restrict__ mask,
                const int* __restrict__ tgt)
{
    __shared__ __align__(16) float U[2][Nn];
    __shared__ unsigned int wmaxbuf[2];
    __shared__ int s_len;

    const int tid = threadIdx.x;                // 0..63
    const int bidx = blockIdx.x;                // 256 blocks: (seq-channel) x (dir)
    const int dir = bidx & 1;
    const int sc = bidx >> 1;
    const int c = sc & 1;
    const int b = sc >> 1;
    const int warp = tid >> 5;
    const int lane = tid & 31;
    const int col0 = tid;
    const int col1 = tid + 64;
    const bool sup = (c == 0);

    // ---- sequence length from mask ----
    if (tid == 0) s_len = 0;
    __syncthreads();
    {
        int cnt = 0;
        const int* mrow = mask + b * Tn;
        for (int k = tid; k < Tn; k += 64) cnt += (mrow[k] != 0) ? 1 : 0;
        #pragma unroll
        for (int o = 16; o; o >>= 1) cnt += __shfl_xor_sync(0xffffffffu, cnt, o);
        if (lane == 0) atomicAdd(&s_len, cnt);
    }

    // ---- E operand: 2 contiguous 128-float runs per thread ----
    ulonglong2 Ep0[32], Ep1[32];
    {
        const float* Emat = (dir == 0) ? g_ET : g_E;
        const ulonglong2* e0 = (const ulonglong2*)(Emat + col0 * Nn);
        const ulonglong2* e1 = (const ulonglong2*)(Emat + col1 * Nn);
        #pragma unroll
        for (int k = 0; k < 32; k++) { Ep0[k] = e0[k]; Ep1[k] = e1[k]; }
    }
    const float en0 = g_enexp[col0], en1 = g_enexp[col1];
    const float st0 = g_stexp[col0], st1 = g_stexp[col1];

    const float* emrow0 = em + (b * Tn) * Nn + col0;
    const float* emrow1 = em + (b * Tn) * Nn + col1;
    const int*   tgrow0 = tgt + (b * Tn) * Nn + col0;
    const int*   tgrow1 = tgt + (b * Tn) * Nn + col1;

    __syncthreads();
    int L = s_len;
    if (L < 1) L = 1;
    if (L > Tn) L = Tn;
    const int m = (L >> 1) > 0 ? (L >> 1) : 1;
    const int tendF = m - 1;

    float v0, v1;
    int Sexp = 0;
    int e_pend = 0;
    float inv_pend = 1.0f;

    if (dir == 0) {
        // ================= FORWARD =================
        {
            float pa = __expf(emrow0[0]);
            float pb = __expf(emrow1[0]);
            if (sup) {
                if (tgrow0[0] == 0) pa = 0.0f;
                if (tgrow1[0] == 0) pb = 0.0f;
            }
            v0 = pa * st0;
            v1 = pb * st1;
            U[0][col0] = v0;
            U[0][col1] = v1;
            unsigned int um = max(__float_as_uint(v0), __float_as_uint(v1));
            unsigned int wmu = __reduce_max_sync(0xffffffffu, um);
            if (lane == 0) wmaxbuf[warp] = wmu;
            __syncthreads();
            unsigned int rm = max(wmaxbuf[0], wmaxbuf[1]);
            e_pend = (int)(rm >> 23) - 127;
            inv_pend = __int_as_float((127 - e_pend) << 23);
        }
        if (tendF == 0) goto fin_f;
        {
            float eA0, eA1, eA2, eA3, eB0, eB1, eB2, eB3;
            int tA0, tA1, tA2, tA3, tB0, tB1, tB2, tB3;
            eA0 = emrow0[1 * Nn]; tA0 = tgrow0[1 * Nn];
            eB0 = emrow1[1 * Nn]; tB0 = tgrow1[1 * Nn];
            eA1 = emrow0[2 * Nn]; tA1 = tgrow0[2 * Nn];
            eB1 = emrow1[2 * Nn]; tB1 = tgrow1[2 * Nn];
            eA2 = emrow0[3 * Nn]; tA2 = tgrow0[3 * Nn];
            eB2 = emrow1[3 * Nn]; tB2 = tgrow1[3 * Nn];
            eA3 = emrow0[4 * Nn]; tA3 = tgrow0[4 * Nn];
            eB3 = emrow1[4 * Nn]; tB3 = tgrow1[4 * Nn];
            for (int base = 1; base < Tn; base += 4) {
                FSTEP(base + 0, eA0, tA0, eB0, tB0, 0, 1, 1)
                FSTEP(base + 1, eA1, tA1, eB1, tB1, 1, 0, 0)
                FSTEP(base + 2, eA2, tA2, eB2, tB2, 0, 1, 0)
                FSTEP(base + 3, eA3, tA3, eB3, tB3, 1, 0, 2)
            }
        }
fin_f:
        g_alpha[sc][col0] = v0;
        g_alpha[sc][col1] = v1;
        if (tid == 0) g_sexpF[sc] = Sexp;
    } else {
        // ================= BACKWARD =================
        v0 = en0;
        v1 = en1;
        {
            unsigned int um = max(__float_as_uint(v0), __float_as_uint(v1));
            unsigned int wmu = __reduce_max_sync(0xffffffffu, um);
            if (lane == 0) wmaxbuf[warp] = wmu;
        }
        if (L - 1 < m) goto fin_b;
        {
            const int t0i = L - 1;
            float eA0, eA1, eA2, eA3, eB0, eB1, eB2, eB3;
            int tA0, tA1, tA2, tA3, tB0, tB1, tB2, tB3;
            int i1 = t0i - 1 >= 0 ? t0i - 1 : 0;
            int i2 = t0i - 2 >= 0 ? t0i - 2 : 0;
            int i3 = t0i - 3 >= 0 ? t0i - 3 : 0;
            eA0 = emrow0[t0i * Nn]; tA0 = tgrow0[t0i * Nn];
            eB0 = emrow1[t0i * Nn]; tB0 = tgrow1[t0i * Nn];
            eA1 = emrow0[i1 * Nn];  tA1 = tgrow0[i1 * Nn];
            eB1 = emrow1[i1 * Nn];  tB1 = tgrow1[i1 * Nn];
            eA2 = emrow0[i2 * Nn];  tA2 = tgrow0[i2 * Nn];
            eB2 = emrow1[i2 * Nn];  tB2 = tgrow1[i2 * Nn];
            eA3 = emrow0[i3 * Nn];  tA3 = tgrow0[i3 * Nn];
            eB3 = emrow1[i3 * Nn];  tB3 = tgrow1[i3 * Nn];
            for (int t0 = t0i; t0 >= 1; t0 -= 4) {
                BSTEP(t0 - 0, eA0, tA0, eB0, tB0, 0, 1)
                BSTEP(t0 - 1, eA1, tA1, eB1, tB1, 1, 0)
                BSTEP(t0 - 2, eA2, tA2, eB2, tB2, 0, 0)
                BSTEP(t0 - 3, eA3, tA3, eB3, tB3, 1, 2)
            }
        }
fin_b:
        g_wvec[sc][col0] = v0;
        g_wvec[sc][col1] = v1;
        if (tid == 0) g_sexpB[sc] = Sexp;
    }
}

#undef FSTEP
#undef BSTEP
#undef MATVEC2

// Combine: z_c = (SexpF+SexpB)*ln2 + log(alpha . w);  loss[b] = z_part - z_sup.
__global__ void combine_kernel(float* __restrict__ out)
{
    __shared__ float zpA[4], zpB[4];
    const int b = blockIdx.x;
    const int j = threadIdx.x;
    const int warp = j >> 5;
    const int lane = j & 31;
    const int scA = (b << 1);
    const int scB = scA | 1;

    float dA = g_alpha[scA][j] * g_wvec[scA][j];
    float dB = g_alpha[scB][j] * g_wvec[scB][j];
    #pragma unroll
    for (int o = 16; o; o >>= 1) {
        dA += __shfl_xor_sync(0xffffffffu, dA, o);
        dB += __shfl_xor_sync(0xffffffffu, dB, o);
    }
    if (lane == 0) { zpA[warp] = dA; zpB[warp] = dB; }
    __syncthreads();
    if (j == 0) {
        float sA = (zpA[0] + zpA[1]) + (zpA[2] + zpA[3]);
        float sB = (zpB[0] + zpB[1]) + (zpB[2] + zpB[3]);
        double zA = (double)(g_sexpF[scA] + g_sexpB[scA]) * 0.6931471805599453
                  + (double)logf(sA);
        double zB = (double)(g_sexpF[scB] + g_sexpB[scB]) * 0.6931471805599453
                  + (double)logf(sB);
        out[b] = (float)(zB - zA);
    }
}

extern "C" void kernel_launch(void* const* d_in, const int* in_sizes, int n_in,
                              void* d_out, int out_size)
{
    const float* em    = (const float*)d_in[0];
    const int*   mask  = (const int*)d_in[1];
    const int*   tgt   = (const int*)d_in[2];
    const float* trans = (const float*)d_in[3];
    const float* st    = (const float*)d_in[4];
    const float* en    = (const float*)d_in[5];
    const int*   ftr   = (const int*)d_in[6];
    const int*   fst   = (const int*)d_in[7];
    const int*   fen   = (const int*)d_in[8];
    float* out = (float*)d_out;

    prep_kernel<<<64, 256>>>(trans, st, en, ftr, fst, fen);
    crf_scan_kernel<<<4 * Bn, 64>>>(em, mask, tgt);
    combine_kernel<<<Bn, 128>>>(out);
}

// round 11
// speedup vs baseline: 2.2842x; 2.2842x over previous
#include <cuda_runtime.h>

#define Nn 128
#define Tn 2048
#define Bn 64

// Precomputed exp-domain constants (written by prep_kernel each launch).
__device__ __align__(16) float g_ET[Nn * Nn];  // ET[j*N+i] (col-major: fwd)
__device__ __align__(16) float g_E[Nn * Nn];   // E[i*N+j]  (row-major: bwd)
__device__ float g_stexp[Nn];
__device__ float g_enexp[Nn];

// Split-scan scratch.
__device__ __align__(16) float g_alpha[2 * Bn][Nn];
__device__ __align__(16) float g_wvec[2 * Bn][Nn];
__device__ int g_sexpF[2 * Bn];
__device__ int g_sexpB[2 * Bn];

__global__ void prep_kernel(const float* __restrict__ trans,
                            const float* __restrict__ st,
                            const float* __restrict__ en,
                            const int* __restrict__ ftr,
                            const int* __restrict__ fst,
                            const int* __restrict__ fen)
{
    int idx = blockIdx.x * blockDim.x + threadIdx.x;
    if (idx < Nn * Nn) {
        int i = idx >> 7;
        int j = idx & (Nn - 1);
        float x = ftr[idx] ? 0.0f : expf(trans[idx]);
        g_E[idx] = x;
        g_ET[j * Nn + i] = x;
    }
    if (idx < Nn) {
        g_stexp[idx] = fst[idx] ? 0.0f : expf(st[idx]);
        g_enexp[idx] = fen[idx] ? 0.0f : expf(en[idx]);
    }
}

__device__ __forceinline__ unsigned long long ffma2(unsigned long long a,
                                                    unsigned long long b,
                                                    unsigned long long c)
{
    unsigned long long d;
    asm("fma.rn.f32x2 %0, %1, %2, %3;" : "=l"(d) : "l"(a), "l"(b), "l"(c));
    return d;
}

__device__ __forceinline__ unsigned long long addf2(unsigned long long a,
                                                    unsigned long long b)
{
    unsigned long long d;
    asm("add.rn.f32x2 %0, %1, %2;" : "=l"(d) : "l"(a), "l"(b));
    return d;
}

__device__ __forceinline__ float unpack_add(unsigned long long a)
{
    float lo, hi;
    asm("mov.b64 {%0, %1}, %2;" : "=f"(lo), "=f"(hi) : "l"(a));
    return lo + hi;
}

// 128-dim dot: this thread's E column/row (regs) x broadcast vector (smem).
__device__ __forceinline__ float matvec128(const float* __restrict__ Ub,
                                           const ulonglong2* __restrict__ Ep)
{
    const ulonglong2* uvec = (const ulonglong2*)Ub;
    unsigned long long a0 = 0ull, a1 = 0ull, a2 = 0ull, a3 = 0ull;
    unsigned long long a4 = 0ull, a5 = 0ull, a6 = 0ull, a7 = 0ull;
    #pragma unroll
    for (int k = 0; k < 32; k += 4) {
        ulonglong2 u0 = uvec[k];
        ulonglong2 u1 = uvec[k + 1];
        ulonglong2 u2 = uvec[k + 2];
        ulonglong2 u3 = uvec[k + 3];
        a0 = ffma2(Ep[k].x,     u0.x, a0);
        a1 = ffma2(Ep[k].y,     u0.y, a1);
        a2 = ffma2(Ep[k + 1].x, u1.x, a2);
        a3 = ffma2(Ep[k + 1].y, u1.y, a3);
        a4 = ffma2(Ep[k + 2].x, u2.x, a4);
        a5 = ffma2(Ep[k + 2].y, u2.y, a5);
        a6 = ffma2(Ep[k + 3].x, u3.x, a6);
        a7 = ffma2(Ep[k + 3].y, u3.y, a7);
    }
    a0 = addf2(a0, a1); a2 = addf2(a2, a3);
    a4 = addf2(a4, a5); a6 = addf2(a6, a7);
    a0 = addf2(a0, a2); a4 = addf2(a4, a6);
    a0 = addf2(a0, a4);
    return unpack_add(a0);
}

// Forward step. MODE: 0 plain, 1 apply pending scale, 2 compute new block max.
#define FSTEP(TSTEP, EMV, TGV, RB, WB, MODE)                                    \
    {                                                                           \
        float p = __expf(EMV);                                                  \
        if (sup && (TGV) == 0) p = 0.0f;                                        \
        int tp = (TSTEP) + 4; if (tp > Tn - 1) tp = Tn - 1;                     \
        EMV = emrow[tp * Nn]; TGV = tgrow[tp * Nn];                             \
        if ((MODE) == 1) { p *= inv_pend; Sexp += e_pend; }                     \
        float s = matvec128(U[RB], Ep);                                         \
        v = s * p;                                                              \
        U[WB][j] = v;                                                           \
        if ((MODE) == 2) {                                                      \
            unsigned int wmu = __reduce_max_sync(0xffffffffu, __float_as_uint(v)); \
            if (lane == 0) wmaxbuf[warp] = wmu;                                 \
        }                                                                       \
        __syncthreads();                                                        \
        if ((MODE) == 2) {                                                      \
            unsigned int rm = max(max(wmaxbuf[0], wmaxbuf[1]),                  \
                                  max(wmaxbuf[2], wmaxbuf[3]));                 \
            e_pend = (int)(rm >> 23) - 127;                                     \
            inv_pend = __int_as_float((127 - e_pend) << 23);                    \
        }                                                                       \
        if ((TSTEP) == tendF) goto fin_f;                                       \
    }

// Backward step: w_{t-1} = E (p_t o w_t).
#define BSTEP(TSTEP, EMV, TGV, WB, MODE)                                        \
    {                                                                           \
        float p = __expf(EMV);                                                  \
        if (sup && (TGV) == 0) p = 0.0f;                                        \
        int tp = (TSTEP) - 4; if (tp < 0) tp = 0;                               \
        EMV = emrow[tp * Nn]; TGV = tgrow[tp * Nn];                             \
        U[WB][j] = p * v;                                                       \
        __syncthreads();                                                        \
        if ((MODE) == 1) {                                                      \
            unsigned int rm = max(max(wmaxbuf[0], wmaxbuf[1]),                  \
                                  max(wmaxbuf[2], wmaxbuf[3]));                 \
            e_pend = (int)(rm >> 23) - 127;                                     \
            inv_pend = __int_as_float((127 - e_pend) << 23);                    \
            float s = matvec128(U[WB], Ep);                                     \
            v = s * inv_pend;                                                   \
            Sexp += e_pend;                                                     \
        } else {                                                                \
            v = matvec128(U[WB], Ep);                                           \
        }                                                                       \
        if ((MODE) == 2) {                                                      \
            unsigned int wmu = __reduce_max_sync(0xffffffffu, __float_as_uint(v)); \
            if (lane == 0) wmaxbuf[warp] = wmu;                                 \
        }                                                                       \
        if ((TSTEP) == m) goto fin_b;                                           \
    }

__global__ void __launch_bounds__(128, 2)
crf_scan_kernel(const float* __restrict__ em,
                const int* __restrict__ mask,
                const int* __restrict__ tgt)
{
    __shared__ __align__(16) float U[2][Nn];
    __shared__ unsigned int wmaxbuf[4];
    __shared__ int s_len;

    const int tid = threadIdx.x;
    const int bidx = blockIdx.x;        // 256 blocks: (seq-channel) x (dir)
    const int dir = bidx & 1;           // 0 fwd, 1 bwd
    const int sc = bidx >> 1;
    const int c = sc & 1;               // 0 supervised, 1 partition
    const int b = sc >> 1;
    const int j = tid;
    const int warp = tid >> 5;
    const int lane = tid & 31;
    const bool sup = (c == 0);

    // ---- sequence length from mask ----
    if (tid == 0) s_len = 0;
    __syncthreads();
    {
        int cnt = 0;
        const int* mrow = mask + b * Tn;
        for (int k = tid; k < Tn; k += 128) cnt += (mrow[k] != 0) ? 1 : 0;
        #pragma unroll
        for (int o = 16; o; o >>= 1) cnt += __shfl_xor_sync(0xffffffffu, cnt, o);
        if (lane == 0) atomicAdd(&s_len, cnt);
    }

    // ---- E operand: contiguous 128-float run per thread ----
    ulonglong2 Ep[32];
    {
        const float* Emat = (dir == 0) ? g_ET : g_E;
        const ulonglong2* erow = (const ulonglong2*)(Emat + j * Nn);
        #pragma unroll
        for (int k = 0; k < 32; k++) Ep[k] = erow[k];
    }
    const float enj = g_enexp[j];
    const float stj = g_stexp[j];

    const float* emrow = em + (b * Tn) * Nn + j;
    const int*   tgrow = tgt + (b * Tn) * Nn + j;

    __syncthreads();
    int L = s_len;
    if (L < 1) L = 1;
    if (L > Tn) L = Tn;
    const int m = (L >> 1) > 0 ? (L >> 1) : 1;
    const int tendF = m - 1;

    float v;
    int Sexp = 0;
    int e_pend = 0;
    float inv_pend = 1.0f;

    if (dir == 0) {
        // ================= FORWARD: alpha_{m-1} =================
        {
            float p = __expf(emrow[0]);
            if (sup && tgrow[0] == 0) p = 0.0f;
            v = p * stj;
            U[0][j] = v;
            unsigned int wmu = __reduce_max_sync(0xffffffffu, __float_as_uint(v));
            if (lane == 0) wmaxbuf[warp] = wmu;
            __syncthreads();
            unsigned int rm = max(max(wmaxbuf[0], wmaxbuf[1]),
                                  max(wmaxbuf[2], wmaxbuf[3]));
            e_pend = (int)(rm >> 23) - 127;
            inv_pend = __int_as_float((127 - e_pend) << 23);
        }
        if (tendF == 0) goto fin_f;
        {
            float em0, em1, em2, em3;
            int tg0, tg1, tg2, tg3;
            em0 = emrow[1 * Nn]; tg0 = tgrow[1 * Nn];
            em1 = emrow[2 * Nn]; tg1 = tgrow[2 * Nn];
            em2 = emrow[3 * Nn]; tg2 = tgrow[3 * Nn];
            em3 = emrow[4 * Nn]; tg3 = tgrow[4 * Nn];
            // Renorm once per 8 steps: MODE [1,0,0,0, 0,0,0,2].
            for (int base = 1; base < Tn; base += 8) {
                FSTEP(base + 0, em0, tg0, 0, 1, 1)
                FSTEP(base + 1, em1, tg1, 1, 0, 0)
                FSTEP(base + 2, em2, tg2, 0, 1, 0)
                FSTEP(base + 3, em3, tg3, 1, 0, 0)
                FSTEP(base + 4, em0, tg0, 0, 1, 0)
                FSTEP(base + 5, em1, tg1, 1, 0, 0)
                FSTEP(base + 6, em2, tg2, 0, 1, 0)
                FSTEP(base + 7, em3, tg3, 1, 0, 2)
            }
        }
fin_f:
        g_alpha[sc][j] = v;
        if (tid == 0) g_sexpF[sc] = Sexp;
    } else {
        // ================= BACKWARD: w_{m-1} =================
        v = enj;
        {
            unsigned int wmu = __reduce_max_sync(0xffffffffu, __float_as_uint(v));
            if (lane == 0) wmaxbuf[warp] = wmu;   // published by first BSTEP's bar
        }
        if (L - 1 < m) goto fin_b;
        {
            const int t0i = L - 1;
            int i1 = t0i - 1 >= 0 ? t0i - 1 : 0;
            int i2 = t0i - 2 >= 0 ? t0i - 2 : 0;
            int i3 = t0i - 3 >= 0 ? t0i - 3 : 0;
            float em0, em1, em2, em3;
            int tg0, tg1, tg2, tg3;
            em0 = emrow[t0i * Nn]; tg0 = tgrow[t0i * Nn];
            em1 = emrow[i1 * Nn];  tg1 = tgrow[i1 * Nn];
            em2 = emrow[i2 * Nn];  tg2 = tgrow[i2 * Nn];
            em3 = emrow[i3 * Nn];  tg3 = tgrow[i3 * Nn];
            for (int t0 = t0i; t0 >= 1; t0 -= 8) {
                BSTEP(t0 - 0, em0, tg0, 0, 1)
                BSTEP(t0 - 1, em1, tg1, 1, 0)
                BSTEP(t0 - 2, em2, tg2, 0, 0)
                BSTEP(t0 - 3, em3, tg3, 1, 0)
                BSTEP(t0 - 4, em0, tg0, 0, 0)
                BSTEP(t0 - 5, em1, tg1, 1, 0)
                BSTEP(t0 - 6, em2, tg2, 0, 0)
                BSTEP(t0 - 7, em3, tg3, 1, 2)
            }
        }
fin_b:
        g_wvec[sc][j] = v;
        if (tid == 0) g_sexpB[sc] = Sexp;
    }
}

#undef FSTEP
#undef BSTEP

// Combine: z_c = (SexpF+SexpB)*ln2 + log(alpha . w);  loss[b] = z_part - z_sup.
__global__ void combine_kernel(float* __restrict__ out)
{
    __shared__ float zpA[4], zpB[4];
    const int b = blockIdx.x;
    const int j = threadIdx.x;
    const int warp = j >> 5;
    const int lane = j & 31;
    const int scA = (b << 1);
    const int scB = scA | 1;

    float dA = g_alpha[scA][j] * g_wvec[scA][j];
    float dB = g_alpha[scB][j] * g_wvec[scB][j];
    #pragma unroll
    for (int o = 16; o; o >>= 1) {
        dA += __shfl_xor_sync(0xffffffffu, dA, o);
        dB += __shfl_xor_sync(0xffffffffu, dB, o);
    }
    if (lane == 0) { zpA[warp] = dA; zpB[warp] = dB; }
    __syncthreads();
    if (j == 0) {
        float sA = (zpA[0] + zpA[1]) + (zpA[2] + zpA[3]);
        float sB = (zpB[0] + zpB[1]) + (zpB[2] + zpB[3]);
        double zA = (double)(g_sexpF[scA] + g_sexpB[scA]) * 0.6931471805599453
                  + (double)logf(sA);
        double zB = (double)(g_sexpF[scB] + g_sexpB[scB]) * 0.6931471805599453
                  + (double)logf(sB);
        out[b] = (float)(zB - zA);
    }
}

extern "C" void kernel_launch(void* const* d_in, const int* in_sizes, int n_in,
                              void* d_out, int out_size)
{
    const float* em    = (const float*)d_in[0];
    const int*   mask  = (const int*)d_in[1];
    const int*   tgt   = (const int*)d_in[2];
    const float* trans = (const float*)d_in[3];
    const float* st    = (const float*)d_in[4];
    const float* en    = (const float*)d_in[5];
    const int*   ftr   = (const int*)d_in[6];
    const int*   fst   = (const int*)d_in[7];
    const int*   fen   = (const int*)d_in[8];
    float* out = (float*)d_out;

    prep_kernel<<<64, 256>>>(trans, st, en, ftr, fst, fen);
    crf_scan_kernel<<<4 * Bn, 128>>>(em, mask, tgt);
    combine_kernel<<<Bn, 128>>>(out);
}

// round 12
// speedup vs baseline: 3.3326x; 1.4590x over previous
#include <cuda_runtime.h>

#define Nn 128
#define Tn 2048
#define Bn 64

// Precomputed exp-domain constants (written by prep_kernel each launch).
__device__ __align__(16) float g_ET[Nn * Nn];  // ET[j*N+i] (col-major: fwd)
__device__ __align__(16) float g_E[Nn * Nn];   // E[i*N+j]  (row-major: bwd)
__device__ float g_stexp[Nn];
__device__ float g_enexp[Nn];

// Split-scan scratch.
__device__ __align__(16) float g_alpha[2 * Bn][Nn];
__device__ __align__(16) float g_wvec[2 * Bn][Nn];
__device__ int g_sexpF[2 * Bn];
__device__ int g_sexpB[2 * Bn];

__global__ void prep_kernel(const float* __restrict__ trans,
                            const float* __restrict__ st,
                            const float* __restrict__ en,
                            const int* __restrict__ ftr,
                            const int* __restrict__ fst,
                            const int* __restrict__ fen)
{
    int idx = blockIdx.x * blockDim.x + threadIdx.x;
    if (idx < Nn * Nn) {
        int i = idx >> 7;
        int j = idx & (Nn - 1);
        float x = ftr[idx] ? 0.0f : expf(trans[idx]);
        g_E[idx] = x;
        g_ET[j * Nn + i] = x;
    }
    if (idx < Nn) {
        g_stexp[idx] = fst[idx] ? 0.0f : expf(st[idx]);
        g_enexp[idx] = fen[idx] ? 0.0f : expf(en[idx]);
    }
}

__device__ __forceinline__ unsigned long long ffma2(unsigned long long a,
                                                    unsigned long long b,
                                                    unsigned long long c)
{
    unsigned long long d;
    asm("fma.rn.f32x2 %0, %1, %2, %3;" : "=l"(d) : "l"(a), "l"(b), "l"(c));
    return d;
}

__device__ __forceinline__ unsigned long long addf2(unsigned long long a,
                                                    unsigned long long b)
{
    unsigned long long d;
    asm("add.rn.f32x2 %0, %1, %2;" : "=l"(d) : "l"(a), "l"(b));
    return d;
}

__device__ __forceinline__ float unpack_add(unsigned long long a)
{
    float lo, hi;
    asm("mov.b64 {%0, %1}, %2;" : "=f"(lo), "=f"(hi) : "l"(a));
    return lo + hi;
}

// 128-dim dot: this thread's E column/row (regs) x broadcast vector (smem).
__device__ __forceinline__ float matvec128(const float* __restrict__ Ub,
                                           const ulonglong2* __restrict__ Ep)
{
    const ulonglong2* uvec = (const ulonglong2*)Ub;
    unsigned long long a0 = 0ull, a1 = 0ull, a2 = 0ull, a3 = 0ull;
    unsigned long long a4 = 0ull, a5 = 0ull, a6 = 0ull, a7 = 0ull;
    #pragma unroll
    for (int k = 0; k < 32; k += 4) {
        ulonglong2 u0 = uvec[k];
        ulonglong2 u1 = uvec[k + 1];
        ulonglong2 u2 = uvec[k + 2];
        ulonglong2 u3 = uvec[k + 3];
        a0 = ffma2(Ep[k].x,     u0.x, a0);
        a1 = ffma2(Ep[k].y,     u0.y, a1);
        a2 = ffma2(Ep[k + 1].x, u1.x, a2);
        a3 = ffma2(Ep[k + 1].y, u1.y, a3);
        a4 = ffma2(Ep[k + 2].x, u2.x, a4);
        a5 = ffma2(Ep[k + 2].y, u2.y, a5);
        a6 = ffma2(Ep[k + 3].x, u3.x, a6);
        a7 = ffma2(Ep[k + 3].y, u3.y, a7);
    }
    a0 = addf2(a0, a1); a2 = addf2(a2, a3);
    a4 = addf2(a4, a5); a6 = addf2(a6, a7);
    a0 = addf2(a0, a2); a4 = addf2(a4, a6);
    a0 = addf2(a0, a4);
    return unpack_add(a0);
}

// Forward step (no exit branch: the forward loop is exactly counted).
// MODE: 0 plain, 1 apply pending scale, 2 compute new block max.
#define FSTEP(TSTEP, EMV, TGV, RB, WB, MODE)                                    \
    {                                                                           \
        float p = __expf(EMV);                                                  \
        if (sup && (TGV) == 0) p = 0.0f;                                        \
        const int tp = (TSTEP) + 4;                                             \
        if (tp < Tn) { EMV = emrow[tp * Nn]; TGV = tgrow[tp * Nn]; }            \
        if ((MODE) == 1) { p *= inv_pend; Sexp += e_pend; }                     \
        float s = matvec128(U[RB], Ep);                                         \
        v = s * p;                                                              \
        U[WB][j] = v;                                                           \
        if ((MODE) == 2) {                                                      \
            unsigned int wmu = __reduce_max_sync(0xffffffffu, __float_as_uint(v)); \
            if (lane == 0) wmaxbuf[warp] = wmu;                                 \
        }                                                                       \
        __syncthreads();                                                        \
        if ((MODE) == 2) {                                                      \
            unsigned int rm = max(max(wmaxbuf[0], wmaxbuf[1]),                  \
                                  max(wmaxbuf[2], wmaxbuf[3]));                 \
            e_pend = (int)(rm >> 23) - 127;                                     \
            inv_pend = __int_as_float((127 - e_pend) << 23);                    \
        }                                                                       \
    }

// Backward step: w_{t-1} = E (p_t o w_t). Keeps the per-step exit check.
#define BSTEP(TSTEP, EMV, TGV, WB, MODE)                                        \
    {                                                                           \
        float p = __expf(EMV);                                                  \
        if (sup && (TGV) == 0) p = 0.0f;                                        \
        const int tp = (TSTEP) - 4;                                             \
        if (tp >= 0) { EMV = emrow[tp * Nn]; TGV = tgrow[tp * Nn]; }            \
        U[WB][j] = p * v;                                                       \
        __syncthreads();                                                        \
        if ((MODE) == 1) {                                                      \
            unsigned int rm = max(max(wmaxbuf[0], wmaxbuf[1]),                  \
                                  max(wmaxbuf[2], wmaxbuf[3]));                 \
            e_pend = (int)(rm >> 23) - 127;                                     \
            inv_pend = __int_as_float((127 - e_pend) << 23);                    \
            float s = matvec128(U[WB], Ep);                                     \
            v = s * inv_pend;                                                   \
            Sexp += e_pend;                                                     \
        } else {                                                                \
            v = matvec128(U[WB], Ep);                                           \
        }                                                                       \
        if ((MODE) == 2) {                                                      \
            unsigned int wmu = __reduce_max_sync(0xffffffffu, __float_as_uint(v)); \
            if (lane == 0) wmaxbuf[warp] = wmu;                                 \
        }                                                                       \
        if ((TSTEP) == m) goto fin_b;                                           \
    }

__global__ void __launch_bounds__(128, 2)
crf_scan_kernel(const float* __restrict__ em,
                const int* __restrict__ mask,
                const int* __restrict__ tgt)
{
    __shared__ __align__(16) float U[2][Nn];
    __shared__ unsigned int wmaxbuf[4];
    __shared__ int s_len;

    const int tid = threadIdx.x;
    const int bidx = blockIdx.x;        // 256 blocks: (seq-channel) x (dir)
    const int dir = bidx & 1;           // 0 fwd, 1 bwd
    const int sc = bidx >> 1;
    const int c = sc & 1;               // 0 supervised, 1 partition
    const int b = sc >> 1;
    const int j = tid;
    const int warp = tid >> 5;
    const int lane = tid & 31;
    const bool sup = (c == 0);

    // ---- sequence length from mask ----
    if (tid == 0) s_len = 0;
    __syncthreads();
    {
        int cnt = 0;
        const int* mrow = mask + b * Tn;
        for (int k = tid; k < Tn; k += 128) cnt += (mrow[k] != 0) ? 1 : 0;
        #pragma unroll
        for (int o = 16; o; o >>= 1) cnt += __shfl_xor_sync(0xffffffffu, cnt, o);
        if (lane == 0) atomicAdd(&s_len, cnt);
    }

    // ---- E operand: contiguous 128-float run per thread ----
    ulonglong2 Ep[32];
    {
        const float* Emat = (dir == 0) ? g_ET : g_E;
        const ulonglong2* erow = (const ulonglong2*)(Emat + j * Nn);
        #pragma unroll
        for (int k = 0; k < 32; k++) Ep[k] = erow[k];
    }
    const float enj = g_enexp[j];
    const float stj = g_stexp[j];

    const float* emrow = em + (b * Tn) * Nn + j;
    const int*   tgrow = tgt + (b * Tn) * Nn + j;

    __syncthreads();
    int L = s_len;
    if (L < 1) L = 1;
    if (L > Tn) L = Tn;
    // Split point aligned so tendF = m-1 is a multiple of 4: the forward loop
    // is exactly counted and needs NO per-step exit branches.
    // m = ((L>>1) & ~3) | 1  =>  1 <= m <= L-1 for all L >= 2; m = 1 for L = 1.
    const int m = (((L >> 1) & ~3) | 1);
    const int tendF = m - 1;

    float v;
    int Sexp = 0;
    int e_pend = 0;
    float inv_pend = 1.0f;

    if (dir == 0) {
        // ================= FORWARD: alpha_{m-1} =================
        {
            float p = __expf(emrow[0]);
            if (sup && tgrow[0] == 0) p = 0.0f;
            v = p * stj;
            U[0][j] = v;
            unsigned int wmu = __reduce_max_sync(0xffffffffu, __float_as_uint(v));
            if (lane == 0) wmaxbuf[warp] = wmu;
            __syncthreads();
            unsigned int rm = max(max(wmaxbuf[0], wmaxbuf[1]),
                                  max(wmaxbuf[2], wmaxbuf[3]));
            e_pend = (int)(rm >> 23) - 127;
            inv_pend = __int_as_float((127 - e_pend) << 23);
        }
        if (tendF > 0) {
            float em0, em1, em2, em3;
            int tg0, tg1, tg2, tg3;
            em0 = emrow[1 * Nn]; tg0 = tgrow[1 * Nn];
            em1 = emrow[2 * Nn]; tg1 = tgrow[2 * Nn];
            em2 = emrow[3 * Nn]; tg2 = tgrow[3 * Nn];
            em3 = emrow[4 * Nn]; tg3 = tgrow[4 * Nn];
            // Exactly counted: covers t = 1 .. tendF (tendF % 4 == 0).
            for (int base = 1; base + 3 <= tendF; base += 4) {
                FSTEP(base + 0, em0, tg0, 0, 1, 1)
                FSTEP(base + 1, em1, tg1, 1, 0, 0)
                FSTEP(base + 2, em2, tg2, 0, 1, 0)
                FSTEP(base + 3, em3, tg3, 1, 0, 2)
            }
        }
        g_alpha[sc][j] = v;
        if (tid == 0) g_sexpF[sc] = Sexp;
    } else {
        // ================= BACKWARD: w_{m-1} =================
        v = enj;
        {
            unsigned int wmu = __reduce_max_sync(0xffffffffu, __float_as_uint(v));
            if (lane == 0) wmaxbuf[warp] = wmu;   // published by first BSTEP's bar
        }
        if (L - 1 < m) goto fin_b;
        {
            const int t0i = L - 1;
            int i1 = t0i - 1 >= 0 ? t0i - 1 : 0;
            int i2 = t0i - 2 >= 0 ? t0i - 2 : 0;
            int i3 = t0i - 3 >= 0 ? t0i - 3 : 0;
            float em0, em1, em2, em3;
            int tg0, tg1, tg2, tg3;
            em0 = emrow[t0i * Nn]; tg0 = tgrow[t0i * Nn];
            em1 = emrow[i1 * Nn];  tg1 = tgrow[i1 * Nn];
            em2 = emrow[i2 * Nn];  tg2 = tgrow[i2 * Nn];
            em3 = emrow[i3 * Nn];  tg3 = tgrow[i3 * Nn];
            for (int t0 = t0i; t0 >= 1; t0 -= 4) {
                BSTEP(t0 - 0, em0, tg0, 0, 1)
                BSTEP(t0 - 1, em1, tg1, 1, 0)
                BSTEP(t0 - 2, em2, tg2, 0, 0)
                BSTEP(t0 - 3, em3, tg3, 1, 2)
            }
        }
fin_b:
        g_wvec[sc][j] = v;
        if (tid == 0) g_sexpB[sc] = Sexp;
    }
}

#undef FSTEP
#undef BSTEP

// Combine: z_c = (SexpF+SexpB)*ln2 + log(alpha . w);  loss[b] = z_part - z_sup.
__global__ void combine_kernel(float* __restrict__ out)
{
    __shared__ float zpA[4], zpB[4];
    const int b = blockIdx.x;
    const int j = threadIdx.x;
    const int warp = j >> 5;
    const int lane = j & 31;
    const int scA = (b << 1);
    const int scB = scA | 1;

    float dA = g_alpha[scA][j] * g_wvec[scA][j];
    float dB = g_alpha[scB][j] * g_wvec[scB][j];
    #pragma unroll
    for (int o = 16; o; o >>= 1) {
        dA += __shfl_xor_sync(0xffffffffu, dA, o);
        dB += __shfl_xor_sync(0xffffffffu, dB, o);
    }
    if (lane == 0) { zpA[warp] = dA; zpB[warp] = dB; }
    __syncthreads();
    if (j == 0) {
        float sA = (zpA[0] + zpA[1]) + (zpA[2] + zpA[3]);
        float sB = (zpB[0] + zpB[1]) + (zpB[2] + zpB[3]);
        double zA = (double)(g_sexpF[scA] + g_sexpB[scA]) * 0.6931471805599453
                  + (double)logf(sA);
        double zB = (double)(g_sexpF[scB] + g_sexpB[scB]) * 0.6931471805599453
                  + (double)logf(sB);
        out[b] = (float)(zB - zA);
    }
}

extern "C" void kernel_launch(void* const* d_in, const int* in_sizes, int n_in,
                              void* d_out, int out_size)
{
    const float* em    = (const float*)d_in[0];
    const int*   mask  = (const int*)d_in[1];
    const int*   tgt   = (const int*)d_in[2];
    const float* trans = (const float*)d_in[3];
    const float* st    = (const float*)d_in[4];
    const float* en    = (const float*)d_in[5];
    const int*   ftr   = (const int*)d_in[6];
    const int*   fst   = (const int*)d_in[7];
    const int*   fen   = (const int*)d_in[8];
    float* out = (float*)d_out;

    prep_kernel<<<64, 256>>>(trans, st, en, ftr, fst, fen);
    crf_scan_kernel<<<4 * Bn, 128>>>(em, mask, tgt);
    combine_kernel<<<Bn, 128>>>(out);
}